// round 3
// baseline (speedup 1.0000x reference)
#include <cuda_runtime.h>
#include <math_constants.h>

#define FRAMES 16384
#define JOINTS 22
#define FELEM  (JOINTS * 3)   // 66 floats per frame per motion
#define NPAIR  25
#define NSEG   16
#define TPAD   17              // padded row stride for term[] (bank-conflict-free)

// Segment tables: 16 segments over the 5 paths (seg counts 3,3,4,3,3).
__constant__ int c_seg_s[NSEG] = {2,5,8,  1,4,7,  3,6,9,12,  14,17,19,  13,16,18};
__constant__ int c_seg_e[NSEG] = {5,8,11, 4,7,10, 6,9,12,15, 17,19,21,  16,18,20};
__constant__ int c_off[6]      = {0,3,6,10,13,16};

// Scratch (allocation-free rule: __device__ globals).
__device__ float         g_gli[FRAMES * NPAIR];
__device__ unsigned char g_ov[FRAMES];

struct F3 { float x, y, z; };
__device__ __forceinline__ F3 f3sub(F3 a, F3 b) { return {a.x-b.x, a.y-b.y, a.z-b.z}; }
__device__ __forceinline__ F3 f3cross(F3 a, F3 b) {
    return {a.y*b.z - a.z*b.y, a.z*b.x - a.x*b.z, a.x*b.y - a.y*b.x};
}
__device__ __forceinline__ float f3dot(F3 a, F3 b) { return a.x*b.x + a.y*b.y + a.z*b.z; }
__device__ __forceinline__ float clamp1(float x) { return fminf(fmaxf(x, -1.0f), 1.0f); }

__device__ __forceinline__ F3 ldpt(const float* s, int j) {
    return {s[j*3 + 0], s[j*3 + 1], s[j*3 + 2]};
}

// asin(clamp(dot(a,b)/(|a||b|))) with _safe_normalize semantics:
// zero-norm face -> normalized dot is 0 -> asin = 0.
__device__ __forceinline__ float face_angle(F3 a, F3 b, float da, float db) {
    float dp = da * db;
    float s  = (dp > 0.0f) ? rsqrtf(dp) : 0.0f;
    return asinf(clamp1(f3dot(a, b) * s));
}

// Kernel A: one block (256 threads) per frame; one thread per segment-pair term.
__global__ void __launch_bounds__(256)
gli_frame_kernel(const float* __restrict__ m1, const float* __restrict__ m2) {
    const int frame = blockIdx.x;
    const int tid   = threadIdx.x;

    __shared__ float s1[FELEM];
    __shared__ float s2[FELEM];
    __shared__ float term[NSEG * TPAD];

    const float* f1 = m1 + frame * FELEM;
    const float* f2 = m2 + frame * FELEM;
    if (tid < FELEM) {
        s1[tid] = f1[tid];
        s2[tid] = f2[tid];
    }
    __syncthreads();

    // ---- warp 0 FIRST does the bbox overlap flag (8 shfl rounds; dual-issues
    //      against other warps' FMA streams, keeping warp 0 off the critical path) ----
    if (tid < 32) {
        const bool valid = tid < JOINTS;
        float x1 = valid ? s1[tid*3 + 0] :  CUDART_INF_F;
        float z1 = valid ? s1[tid*3 + 2] :  CUDART_INF_F;
        float x2 = valid ? s2[tid*3 + 0] :  CUDART_INF_F;
        float z2 = valid ? s2[tid*3 + 2] :  CUDART_INF_F;
        float x1n = x1, z1n = z1, x2n = x2, z2n = z2;
        float x1x = valid ? x1 : -CUDART_INF_F;
        float z1x = valid ? z1 : -CUDART_INF_F;
        float x2x = valid ? x2 : -CUDART_INF_F;
        float z2x = valid ? z2 : -CUDART_INF_F;
        #pragma unroll
        for (int o = 16; o > 0; o >>= 1) {
            x1n = fminf(x1n, __shfl_xor_sync(0xFFFFFFFFu, x1n, o));
            x1x = fmaxf(x1x, __shfl_xor_sync(0xFFFFFFFFu, x1x, o));
            z1n = fminf(z1n, __shfl_xor_sync(0xFFFFFFFFu, z1n, o));
            z1x = fmaxf(z1x, __shfl_xor_sync(0xFFFFFFFFu, z1x, o));
            x2n = fminf(x2n, __shfl_xor_sync(0xFFFFFFFFu, x2n, o));
            x2x = fmaxf(x2x, __shfl_xor_sync(0xFFFFFFFFu, x2x, o));
            z2n = fminf(z2n, __shfl_xor_sync(0xFFFFFFFFu, z2n, o));
            z2x = fmaxf(z2x, __shfl_xor_sync(0xFFFFFFFFu, z2x, o));
        }
        if (tid == 0) {
            bool ovx = !((x1x < x2n) || (x2x < x1n));
            bool ovz = !((z1x < z2n) || (z2x < z1n));
            g_ov[frame] = (ovx && ovz) ? 1 : 0;
        }
    }

    // ---- one GLI term per thread: i = motion1 segment, j = motion2 segment ----
    {
        const int i = tid >> 4;
        const int j = tid & 15;
        const F3 s1p = ldpt(s1, c_seg_s[i]);
        const F3 e1p = ldpt(s1, c_seg_e[i]);
        const F3 s2p = ldpt(s2, c_seg_s[j]);
        const F3 e2p = ldpt(s2, c_seg_e[j]);

        const F3 r12 = f3sub(e1p, s1p);
        const F3 r13 = f3sub(s2p, s1p);
        const F3 r14 = f3sub(e2p, s1p);
        const F3 r23 = f3sub(s2p, e1p);
        const F3 r24 = f3sub(e2p, e1p);
        const F3 r34 = f3sub(e2p, s2p);

        const F3 fc0 = f3cross(r13, r14);
        const F3 fc1 = f3cross(r14, r24);
        const F3 fc2 = f3cross(r24, r23);
        const F3 fc3 = f3cross(r23, r13);
        const float d0 = f3dot(fc0, fc0);
        const float d1 = f3dot(fc1, fc1);
        const float d2 = f3dot(fc2, fc2);
        const float d3 = f3dot(fc3, fc3);

        float g = face_angle(fc0, fc1, d0, d1)
                + face_angle(fc1, fc2, d1, d2)
                + face_angle(fc2, fc3, d2, d3)
                + face_angle(fc3, fc0, d3, d0);

        const float sg = f3dot(f3cross(r34, r12), r13);
        term[i * TPAD + j] = (sg > 0.0f) ? g : -g;
    }
    __syncthreads();

    // ---- deterministic per-pair reduction (reference order: i outer, j inner) ----
    if (tid < NPAIR) {
        const int pa = tid / 5;
        const int pb = tid % 5;
        const int ia0 = c_off[pa], ia1 = c_off[pa + 1];
        const int ib0 = c_off[pb], ib1 = c_off[pb + 1];
        float acc = 0.0f;
        for (int i = ia0; i < ia1; ++i)
            for (int j = ib0; j < ib1; ++j)
                acc += term[i * TPAD + j];
        g_gli[frame * NPAIR + tid] = acc * (1.0f / (4.0f * CUDART_PI_F));
    }
}

// Kernel B: out[f] = max_p | gli[f+1][p]*mask[f+1] - gli[f][p]*mask[f] |
// mask[i] = ov[i] | ov[i-1] | ov[i+1]  (boundaries: false outside)
__device__ __forceinline__ float mask_at(int i) {
    bool m = g_ov[i] != 0;
    if (i > 0)          m = m || (g_ov[i - 1] != 0);
    if (i < FRAMES - 1) m = m || (g_ov[i + 1] != 0);
    return m ? 1.0f : 0.0f;
}

__global__ void __launch_bounds__(256)
vel_kernel(float* __restrict__ out) {
    const int f = blockIdx.x * blockDim.x + threadIdx.x;
    if (f >= FRAMES - 1) return;
    const float m0 = mask_at(f);
    const float m1 = mask_at(f + 1);
    const float* a = g_gli + f * NPAIR;
    const float* b = a + NPAIR;
    float mx = 0.0f;
    #pragma unroll
    for (int p = 0; p < NPAIR; ++p) {
        mx = fmaxf(mx, fabsf(b[p] * m1 - a[p] * m0));
    }
    out[f] = mx;
}

extern "C" void kernel_launch(void* const* d_in, const int* in_sizes, int n_in,
                              void* d_out, int out_size) {
    const float* motion1 = (const float*)d_in[0];
    const float* motion2 = (const float*)d_in[1];
    float* out = (float*)d_out;

    gli_frame_kernel<<<FRAMES, 256>>>(motion1, motion2);

    const int n = FRAMES - 1;
    vel_kernel<<<(n + 255) / 256, 256>>>(out);
}